// round 17
// baseline (speedup 1.0000x reference)
#include <cuda_runtime.h>
#include <cstdint>

// Bidirectional GRU (B=32768, T=18, I=2, H=64) + fc1(128->24) + reshape + fc2(18->2)
// R17: R16 with width-maximized accesses (bit-identical math):
//  - nh / fc1 weight fragments ktpair-packed -> LDS.128 (was LDS.64)
//  - fc2 accumulator as one float4[24] -> LDL/STL.128 (was 2x .64)

#define RZSTRIDE 20            // uint4 per rz-row (16 used + 4 pad), stride%8==4
#define NH4ST    12            // uint4 per nh/fc1 row (8 used + 4 pad), stride%8==4
#define NTHR     512

// ---------- helpers ----------
__device__ __forceinline__ uint32_t pack_f16x2(float a, float b) {
    uint32_t r;
    asm("{.reg .f16 l, h; cvt.rn.f16.f32 l, %1; cvt.rn.f16.f32 h, %2; mov.b32 %0, {l, h};}"
        : "=r"(r) : "f"(a), "f"(b));
    return r;
}
__device__ __forceinline__ uint32_t cvt2(float hi, float lo) {   // lo -> low half
    uint32_t r;
    asm("cvt.rn.f16x2.f32 %0, %1, %2;" : "=r"(r) : "f"(hi), "f"(lo));
    return r;
}
__device__ __forceinline__ uint32_t tanh2(uint32_t x) {
    uint32_t r;
    asm("tanh.approx.f16x2 %0, %1;" : "=r"(r) : "r"(x));
    return r;
}
__device__ __forceinline__ uint32_t hfma2_(uint32_t a, uint32_t b, uint32_t c) {
    uint32_t r;
    asm("fma.rn.f16x2 %0, %1, %2, %3;" : "=r"(r) : "r"(a), "r"(b), "r"(c));
    return r;
}
__device__ __forceinline__ uint32_t hadd2_(uint32_t a, uint32_t b) {
    uint32_t r;
    asm("add.rn.f16x2 %0, %1, %2;" : "=r"(r) : "r"(a), "r"(b));
    return r;
}
__device__ __forceinline__ uint32_t hsub2_(uint32_t a, uint32_t b) {
    uint32_t r;
    asm("sub.rn.f16x2 %0, %1, %2;" : "=r"(r) : "r"(a), "r"(b));
    return r;
}
#define K05 0x38003800u        // (0.5h, 0.5h)

__device__ __forceinline__ void mma_f16(float& c0, float& c1, float& c2, float& c3,
                                        uint32_t a0, uint32_t a1, uint32_t a2, uint32_t a3,
                                        uint32_t b0, uint32_t b1) {
    asm volatile("mma.sync.aligned.m16n8k16.row.col.f32.f16.f16.f32 "
                 "{%0,%1,%2,%3}, {%4,%5,%6,%7}, {%8,%9}, {%0,%1,%2,%3};"
                 : "+f"(c0), "+f"(c1), "+f"(c2), "+f"(c3)
                 : "r"(a0), "r"(a1), "r"(a2), "r"(a3), "r"(b0), "r"(b1));
}
#define MMA4(c, A, b0, b1) mma_f16(c[0], c[1], c[2], c[3], A[0], A[1], A[2], A[3], b0, b1)

// ---------- per-direction step helpers ----------
__device__ __forceinline__ void gate_step(uint32_t A[4][4], uint32_t N[4][4],
                                          const uint32_t a4[4],
                                          const uint4* sRZth, const uint4* sNHp,
                                          const uint4* sRZ4th, const uint2* sNH4th,
                                          const uint32_t* gcB, int qd, bool hasH) {
    #pragma unroll
    for (int g = 0; g < 8; g++) {
        float cr[4] = {0,0,0,0}, cz[4] = {0,0,0,0};
        float ch[4] = {0,0,0,0}, cnx[4] = {0,0,0,0};
        {
            const uint4 w4 = sRZ4th[g * 32];
            MMA4(cr, a4, w4.x, w4.y);
            MMA4(cz, a4, w4.z, w4.w);
            const uint2 v4 = sNH4th[g * 32];
            MMA4(cnx, a4, v4.x, v4.y);
        }
        if (hasH) {
            #pragma unroll
            for (int kt = 0; kt < 4; kt++) {
                const uint4 wrz = sRZth[g * (8 * RZSTRIDE) + kt * 4];
                MMA4(cr, A[kt], wrz.x, wrz.y);
                MMA4(cz, A[kt], wrz.z, wrz.w);
            }
            #pragma unroll
            for (int ktp = 0; ktp < 2; ktp++) {
                const uint4 wnh = sNHp[g * (8 * NH4ST) + ktp * 4];
                MMA4(ch, A[2*ktp],     wnh.x, wnh.y);
                MMA4(ch, A[2*ktp + 1], wnh.z, wnh.w);
            }
        }
        const uint32_t bn2 = gcB[g * 4 + qd];
        const int kt_ = g >> 1, sl = (g & 1) * 2;
        const uint32_t r2a = hfma2_(tanh2(cvt2(cr[1], cr[0])), K05, K05);
        const uint32_t r2b = hfma2_(tanh2(cvt2(cr[3], cr[2])), K05, K05);
        const uint32_t z2a = hfma2_(tanh2(cvt2(cz[1], cz[0])), K05, K05);
        const uint32_t z2b = hfma2_(tanh2(cvt2(cz[3], cz[2])), K05, K05);
        const uint32_t ch2a = hadd2_(cvt2(ch[1], ch[0]), bn2);
        const uint32_t ch2b = hadd2_(cvt2(ch[3], ch[2]), bn2);
        const uint32_t na = tanh2(hfma2_(r2a, ch2a, cvt2(cnx[1], cnx[0])));
        const uint32_t nb = tanh2(hfma2_(r2b, ch2b, cvt2(cnx[3], cnx[2])));
        const uint32_t holda = A[kt_][sl];
        const uint32_t holdb = A[kt_][sl + 1];
        N[kt_][sl]     = hfma2_(z2a, hsub2_(holda, na), na);
        N[kt_][sl + 1] = hfma2_(z2b, hsub2_(holdb, nb), nb);
    }
}

__device__ __forceinline__ void fc1_step(float f[3][4], const uint32_t A[4][4],
                                         const uint4* sF1p) {
    #pragma unroll
    for (int q = 0; q < 3; q++)
        #pragma unroll
        for (int i = 0; i < 4; i++) f[q][i] = 0.0f;
    #pragma unroll
    for (int ktp = 0; ktp < 2; ktp++) {
        #pragma unroll
        for (int q = 0; q < 3; q++) {
            const uint4 w = sF1p[q * (8 * NH4ST) + ktp * 4];
            MMA4(f[q], A[2*ktp],     w.x, w.y);
            MMA4(f[q], A[2*ktp + 1], w.z, w.w);
        }
    }
}

__device__ __forceinline__ void fc2_scatter(float4* acc,
                                            const float f[3][4], int tf,
                                            const int kk[6], const float* fbv, bool addb,
                                            const float2* fc2p) {
    const float vv0[6] = {f[0][0], f[0][1], f[1][0], f[1][1], f[2][0], f[2][1]};
    const float vv8[6] = {f[0][2], f[0][3], f[1][2], f[1][3], f[2][2], f[2][3]};
    #pragma unroll
    for (int j = 0; j < 6; j++) {
        const int n_ = tf * 24 + kk[j];
        const int rr = n_ / 18;
        const int jj = n_ - rr * 18;
        const float2 w2 = fc2p[jj];
        const float fb = addb ? fbv[j] : 0.0f;
        const float va = vv0[j] + fb;
        const float vb = vv8[j] + fb;
        float4 c = acc[rr];
        c.x += va * w2.x;
        c.y += va * w2.y;
        c.z += vb * w2.x;
        c.w += vb * w2.y;
        acc[rr] = c;
    }
}

// ---------- fused kernel: 512 threads, grid 128 ----------
extern __shared__ uint32_t smem_u[];

__global__ __launch_bounds__(NTHR)
void gru_mma_kernel(const float* __restrict__ x,
                    const float* __restrict__ w_ih_f, const float* __restrict__ w_hh_f,
                    const float* __restrict__ b_ih_f, const float* __restrict__ b_hh_f,
                    const float* __restrict__ w_ih_b, const float* __restrict__ w_hh_b,
                    const float* __restrict__ b_ih_b, const float* __restrict__ b_hh_b,
                    const float* __restrict__ fc1_w, const float* __restrict__ fc1_b,
                    const float* __restrict__ fc2_w, const float* __restrict__ fc2_b,
                    float* __restrict__ out) {
    // per-dir smem regions
    uint4*    sRZ   = (uint4*)smem_u;                     // [2][64*RZSTRIDE]
    uint4*    sNH   = sRZ + 2 * 64 * RZSTRIDE;            // [2][64*NH4ST]
    uint4*    sF1   = sNH + 2 * 64 * NH4ST;               // [2][24*NH4ST]
    uint4*    sRZ4  = sF1 + 2 * 24 * NH4ST;               // [2][256]
    uint2*    sNH4  = (uint2*)(sRZ4 + 2 * 256);           // [2][256]
    uint32_t* gcBu  = (uint32_t*)(sNH4 + 2 * 256);        // [2][32]
    float2*   fc2p  = (float2*)(gcBu + 64);               // 18

    const int tid  = threadIdx.x;
    const int warp = tid >> 5;
    const int lane = tid & 31;
    const int qd   = lane & 3;
    const int row0 = blockIdx.x * 256 + warp * 16 + (lane >> 2);   // rows row0, row0+8
    const int thro = (lane >> 2);

    if (tid < 18) fc2p[tid] = make_float2(fc2_w[tid], fc2_w[18 + tid]);

    const int kk0 = qd * 2;
    int kk[6] = {kk0, kk0 + 1, kk0 + 8, kk0 + 9, kk0 + 16, kk0 + 17};
    float fbv[6];
    #pragma unroll
    for (int j = 0; j < 6; j++) fbv[j] = __ldg(fc1_b + kk[j]);

    // fc2 accumulator: {r0c0, r0c1, r8c0, r8c1} (dynamic-indexed -> local, 128-bit RMW)
    float4 acc[24];
    #pragma unroll
    for (int m = 0; m < 24; m++) acc[m] = make_float4(0.f, 0.f, 0.f, 0.f);

    // ---- pack BOTH directions' weights once ----
    #pragma unroll 1
    for (int dir = 0; dir < 2; ++dir) {
        const float* wih = dir ? w_ih_b : w_ih_f;
        const float* whh = dir ? w_hh_b : w_hh_f;
        const float* bih = dir ? b_ih_b : b_ih_f;
        const float* bhh = dir ? b_hh_b : b_hh_f;
        uint4* dRZ  = sRZ  + dir * 64 * RZSTRIDE;
        uint4* dNH  = sNH  + dir * 64 * NH4ST;
        uint4* dF1  = sF1  + dir * 24 * NH4ST;
        uint4* dRZ4 = sRZ4 + dir * 256;
        uint2* dNH4 = sNH4 + dir * 256;

        // rz (per-kt uint4, stride RZSTRIDE), r/z pre-scaled by 0.5
        #pragma unroll 1
        for (int i = tid; i < 64 * 16; i += NTHR) {
            const int n   = i >> 4;
            const int rem = i & 15;
            const int kt  = rem >> 2, q = rem & 3;
            const int kA  = 2 * (q + 8 * kt);
            const int kB  = kA + 8;
            uint4 w;
            w.x = pack_f16x2(0.5f * whh[n * 64 + kA],        0.5f * whh[n * 64 + kA + 1]);
            w.y = pack_f16x2(0.5f * whh[n * 64 + kB],        0.5f * whh[n * 64 + kB + 1]);
            w.z = pack_f16x2(0.5f * whh[(64 + n) * 64 + kA], 0.5f * whh[(64 + n) * 64 + kA + 1]);
            w.w = pack_f16x2(0.5f * whh[(64 + n) * 64 + kB], 0.5f * whh[(64 + n) * 64 + kB + 1]);
            dRZ[n * RZSTRIDE + kt * 4 + q] = w;
        }
        // nh (ktpair uint4, stride NH4ST)
        #pragma unroll 1
        for (int i = tid; i < 64 * 8; i += NTHR) {
            const int n   = i >> 3;
            const int rem = i & 7;
            const int ktp = rem >> 2, q = rem & 3;
            const int kt0 = 2 * ktp, kt1 = kt0 + 1;
            const int kA0 = 2 * (q + 8 * kt0), kB0 = kA0 + 8;
            const int kA1 = 2 * (q + 8 * kt1), kB1 = kA1 + 8;
            const float* wr = whh + (128 + n) * 64;
            uint4 w;
            w.x = pack_f16x2(wr[kA0], wr[kA0 + 1]);
            w.y = pack_f16x2(wr[kB0], wr[kB0 + 1]);
            w.z = pack_f16x2(wr[kA1], wr[kA1 + 1]);
            w.w = pack_f16x2(wr[kB1], wr[kB1 + 1]);
            dNH[n * NH4ST + ktp * 4 + q] = w;
        }
        // fc1 (ktpair uint4, stride NH4ST)
        #pragma unroll 1
        for (int i = tid; i < 24 * 8; i += NTHR) {
            const int n   = i >> 3;
            const int rem = i & 7;
            const int ktp = rem >> 2, q = rem & 3;
            const int kt0 = 2 * ktp, kt1 = kt0 + 1;
            const int kA0 = 2 * (q + 8 * kt0), kB0 = kA0 + 8;
            const int kA1 = 2 * (q + 8 * kt1), kB1 = kA1 + 8;
            const float* fr = fc1_w + n * 128 + 64 * dir;
            uint4 w;
            w.x = pack_f16x2(fr[kA0], fr[kA0 + 1]);
            w.y = pack_f16x2(fr[kB0], fr[kB0 + 1]);
            w.z = pack_f16x2(fr[kA1], fr[kA1 + 1]);
            w.w = pack_f16x2(fr[kB1], fr[kB1 + 1]);
            dF1[n * NH4ST + ktp * 4 + q] = w;
        }
        // kt4 tiles (x + bias); r/z entries pre-scaled by 0.5
        if (tid < 256) {
            const int n = tid >> 2, q = tid & 3;
            uint4 w = make_uint4(0u, 0u, 0u, 0u);
            uint2 v = make_uint2(0u, 0u);
            if (q == 0) {
                w.x = pack_f16x2(0.5f * wih[2*n],        0.5f * wih[2*n + 1]);
                w.z = pack_f16x2(0.5f * wih[2*(64 + n)], 0.5f * wih[2*(64 + n) + 1]);
                v.x = pack_f16x2(wih[2*(128 + n)],       wih[2*(128 + n) + 1]);
            } else if (q == 1) {
                w.x = pack_f16x2(0.5f * (bih[n] + bhh[n]), 0.0f);
                w.z = pack_f16x2(0.5f * (bih[64 + n] + bhh[64 + n]), 0.0f);
                v.x = pack_f16x2(bih[128 + n], 0.0f);
            }
            dRZ4[n * 4 + q] = w;
            dNH4[n * 4 + q] = v;
        }
        if (tid < 32)
            gcBu[dir * 32 + tid] = pack_f16x2(bhh[128 + 2*tid], bhh[128 + 2*tid + 1]);
    }
    __syncthreads();

    // per-thread fragment pointers, both dirs
    const uint4*    sRZ0  = sRZ  + thro * RZSTRIDE + qd;
    const uint4*    sRZ1  = sRZ0 + 64 * RZSTRIDE;
    const uint4*    sNH0  = sNH  + thro * NH4ST + qd;
    const uint4*    sNH1  = sNH0 + 64 * NH4ST;
    const uint4*    sF10  = sF1  + thro * NH4ST + qd;
    const uint4*    sF11  = sF10 + 24 * NH4ST;
    const uint4*    sRZ40 = sRZ4 + thro * 4 + qd;
    const uint4*    sRZ41 = sRZ40 + 256;
    const uint2*    sNH40 = sNH4 + thro * 4 + qd;
    const uint2*    sNH41 = sNH40 + 256;
    const uint32_t* gcB0  = gcBu;
    const uint32_t* gcB1  = gcBu + 32;

    uint32_t A0[4][4], A1[4][4];
    #pragma unroll
    for (int kt = 0; kt < 4; kt++)
        #pragma unroll
        for (int i = 0; i < 4; i++) { A0[kt][i] = 0u; A1[kt][i] = 0u; }

    const float* xr0 = x + (size_t)row0 * 36;
    const float* xr8 = x + (size_t)(row0 + 8) * 36;

    #pragma unroll 1
    for (int s = 0; s < 18; ++s) {
        const int t0 = s;
        const int t1 = 17 - s;

        // ---- build kt4 A fragments for both dirs ----
        uint32_t a40[4] = {0u, 0u, 0u, 0u};
        uint32_t a41[4] = {0u, 0u, 0u, 0u};
        if (qd == 0) {
            const float2 xa0 = *(const float2*)(xr0 + t0 * 2);
            const float2 xb0 = *(const float2*)(xr8 + t0 * 2);
            const float2 xa1 = *(const float2*)(xr0 + t1 * 2);
            const float2 xb1 = *(const float2*)(xr8 + t1 * 2);
            a40[0] = pack_f16x2(xa0.x, xa0.y);
            a40[1] = pack_f16x2(xb0.x, xb0.y);
            a41[0] = pack_f16x2(xa1.x, xa1.y);
            a41[1] = pack_f16x2(xb1.x, xb1.y);
        } else if (qd == 1) {
            a40[0] = a40[1] = 0x00003C00u;   // (1.0h, 0h)
            a41[0] = a41[1] = 0x00003C00u;
        }

        // ---- fc1 on h_{s-1} (old A) for both dirs, then scatter ----
        if (s >= 1) {
            float f0[3][4], f1[3][4];
            fc1_step(f0, A0, sF10);
            fc1_step(f1, A1, sF11);
            fc2_scatter(acc, f0, s - 1,  kk, fbv, true,  fc2p);
            fc2_scatter(acc, f1, 18 - s, kk, fbv, false, fc2p);
        }

        // ---- gate updates, both dirs ----
        uint32_t N0[4][4], N1[4][4];
        gate_step(A0, N0, a40, sRZ0, sNH0, sRZ40, sNH40, gcB0, qd, s > 0);
        gate_step(A1, N1, a41, sRZ1, sNH1, sRZ41, sNH41, gcB1, qd, s > 0);

        #pragma unroll
        for (int kt = 0; kt < 4; kt++)
            #pragma unroll
            for (int i = 0; i < 4; i++) { A0[kt][i] = N0[kt][i]; A1[kt][i] = N1[kt][i]; }
    }

    // ---- s=18: fc1 on h_17 for both dirs ----
    {
        float f0[3][4], f1[3][4];
        fc1_step(f0, A0, sF10);
        fc1_step(f1, A1, sF11);
        fc2_scatter(acc, f0, 17, kk, fbv, true,  fc2p);
        fc2_scatter(acc, f1, 0,  kk, fbv, false, fc2p);
    }

    // ---- quad reduce + write (qd==0 lane per row) ----
    const float b0v = __ldg(fc2_b), b1v = __ldg(fc2_b + 1);
    float* o0 = out + (size_t)row0 * 48;
    float* o8 = out + (size_t)(row0 + 8) * 48;
    #pragma unroll
    for (int p = 0; p < 24; p++) {
        float4 v = acc[p];
        #pragma unroll
        for (int d = 1; d <= 2; d <<= 1) {
            v.x += __shfl_xor_sync(0xffffffffu, v.x, d);
            v.y += __shfl_xor_sync(0xffffffffu, v.y, d);
            v.z += __shfl_xor_sync(0xffffffffu, v.z, d);
            v.w += __shfl_xor_sync(0xffffffffu, v.w, d);
        }
        if (qd == 0) {
            o0[2*p]     = v.x + b0v;
            o0[2*p + 1] = v.y + b1v;
            o8[2*p]     = v.z + b0v;
            o8[2*p + 1] = v.w + b1v;
        }
    }
}

extern "C" void kernel_launch(void* const* d_in, const int* in_sizes, int n_in,
                              void* d_out, int out_size)
{
    const float* x      = (const float*)d_in[0];
    const float* w_ih_f = (const float*)d_in[1];
    const float* w_hh_f = (const float*)d_in[2];
    const float* b_ih_f = (const float*)d_in[3];
    const float* b_hh_f = (const float*)d_in[4];
    const float* w_ih_b = (const float*)d_in[5];
    const float* w_hh_b = (const float*)d_in[6];
    const float* b_ih_b = (const float*)d_in[7];
    const float* b_hh_b = (const float*)d_in[8];
    const float* fc1_w  = (const float*)d_in[9];
    const float* fc1_b  = (const float*)d_in[10];
    const float* fc2_w  = (const float*)d_in[11];
    const float* fc2_b  = (const float*)d_in[12];
    float* out = (float*)d_out;

    const int smem_bytes = 2 * 64 * RZSTRIDE * 16    // sRZ
                         + 2 * 64 * NH4ST * 16       // sNH
                         + 2 * 24 * NH4ST * 16       // sF1
                         + 2 * 256 * 16              // sRZ4
                         + 2 * 256 * 8               // sNH4
                         + 2 * 32 * 4                // gcBu
                         + 18 * 8;                   // fc2p
    cudaFuncSetAttribute(gru_mma_kernel,
                         cudaFuncAttributeMaxDynamicSharedMemorySize, smem_bytes);
    gru_mma_kernel<<<128, NTHR, smem_bytes>>>(
        x, w_ih_f, w_hh_f, b_ih_f, b_hh_f,
        w_ih_b, w_hh_b, b_ih_b, b_hh_b, fc1_w, fc1_b, fc2_w, fc2_b, out);
}